// round 16
// baseline (speedup 1.0000x reference)
#include <cuda_runtime.h>
#include <cuda_bf16.h>
#include <cstdint>
#include <math.h>

// Problem constants
#define BB    2
#define SS    2048
#define HH    4096
#define NHEAD 32
#define DD    128
#define MTOT  (BB*SS)

// Scratch (no cudaMalloc allowed)
__device__ float g_Q[(size_t)BB*SS*HH];        // 64 MB -> Q bf16 hi/lo planes
__device__ float g_attn[(size_t)BB*SS*HH];     // 64 MB -> attn bf16 hi/lo planes
__device__ float g_part[(size_t)8*MTOT*DD];    // 16 MB split-K partials (=4*MTOT*256 floats)
__device__ __nv_bfloat16 g_Asplit[(size_t)2*MTOT*HH];   // X split (hi, lo planes)
__device__ __nv_bfloat16 g_Wsplit[(size_t)2*HH*HH];     // Wq split
__device__ __nv_bfloat16 g_Wsplit2[(size_t)2*HH*HH];    // Wo split
__device__ __nv_bfloat16 g_WsplitKV[(size_t)2*2*DD*HH]; // Wk|Wv combined split (hi plane 256xHH, lo plane)
__device__ __nv_bfloat16 g_Ks[(size_t)2*MTOT*DD];       // K split planes
__device__ __nv_bfloat16 g_Vs[(size_t)2*MTOT*DD];       // V split planes

// ===========================================================================
// Helpers
// ===========================================================================
__device__ __forceinline__ uint32_t smem_u32(const void* p) {
    uint32_t a;
    asm("{ .reg .u64 t; cvta.to.shared.u64 t, %1; cvt.u32.u64 %0, t; }" : "=r"(a) : "l"(p));
    return a;
}
__device__ __forceinline__ void cp_async16(uint32_t dst, const void* src) {
    asm volatile("cp.async.cg.shared.global [%0], [%1], 16;" :: "r"(dst), "l"(src));
}
__device__ __forceinline__ void ldsm_x4(uint32_t& r0, uint32_t& r1, uint32_t& r2,
                                        uint32_t& r3, uint32_t addr) {
    asm volatile("ldmatrix.sync.aligned.m8n8.x4.shared.b16 {%0,%1,%2,%3}, [%4];"
                 : "=r"(r0), "=r"(r1), "=r"(r2), "=r"(r3) : "r"(addr));
}
__device__ __forceinline__ void ldsm_x4_t(uint32_t& r0, uint32_t& r1, uint32_t& r2,
                                          uint32_t& r3, uint32_t addr) {
    asm volatile("ldmatrix.sync.aligned.m8n8.x4.trans.shared.b16 {%0,%1,%2,%3}, [%4];"
                 : "=r"(r0), "=r"(r1), "=r"(r2), "=r"(r3) : "r"(addr));
}
// bf16 mma.sync: D(16x8) += A(16x16) @ B(8x16)^T, row.col, fp32 accum
__device__ __forceinline__ void mma_bf16(float* d, const uint32_t* a, const uint32_t* b) {
    asm volatile(
        "mma.sync.aligned.m16n8k16.row.col.f32.bf16.bf16.f32 "
        "{%0,%1,%2,%3}, {%4,%5,%6,%7}, {%8,%9}, {%0,%1,%2,%3};"
        : "+f"(d[0]), "+f"(d[1]), "+f"(d[2]), "+f"(d[3])
        : "r"(a[0]), "r"(a[1]), "r"(a[2]), "r"(a[3]), "r"(b[0]), "r"(b[1]));
}

__device__ __forceinline__ uint32_t pk2(__nv_bfloat16 a, __nv_bfloat16 b) {
    return (uint32_t)__bfloat16_as_ushort(a) | ((uint32_t)__bfloat16_as_ushort(b) << 16);
}
__device__ __forceinline__ void spl(float v, __nv_bfloat16& h, __nv_bfloat16& l) {
    h = __float2bfloat16(v);
    l = __float2bfloat16(v - __bfloat162float(h));
}

// ===========================================================================
// Pre-pass: split (scale * fp32) into two bf16 planes. 8 elems/thread.
// ===========================================================================
__global__ void __launch_bounds__(256)
split_bf16(const float* __restrict__ in, __nv_bfloat16* __restrict__ hi,
           __nv_bfloat16* __restrict__ lo, int n8, float scale)
{
    int i = blockIdx.x * 256 + threadIdx.x;
    if (i < n8) {
        const float4* p = (const float4*)in;
        float4 a = p[2*i], b = p[2*i+1];
        __nv_bfloat16 h[8], l[8];
        spl(a.x*scale, h[0], l[0]); spl(a.y*scale, h[1], l[1]);
        spl(a.z*scale, h[2], l[2]); spl(a.w*scale, h[3], l[3]);
        spl(b.x*scale, h[4], l[4]); spl(b.y*scale, h[5], l[5]);
        spl(b.z*scale, h[6], l[6]); spl(b.w*scale, h[7], l[7]);
        uint4 H, L;
        H.x = pk2(h[0], h[1]); H.y = pk2(h[2], h[3]);
        H.z = pk2(h[4], h[5]); H.w = pk2(h[6], h[7]);
        L.x = pk2(l[0], l[1]); L.y = pk2(l[2], l[3]);
        L.z = pk2(l[4], l[5]); L.w = pk2(l[6], l[7]);
        ((uint4*)hi)[i] = H;
        ((uint4*)lo)[i] = L;
    }
}

// ===========================================================================
// bf16x3 tensor-core GEMM (R12-validated core, GROUP_M raster).
// Output modes:
//   gridDim.z > 1             : fp32 partials to C + z*M*N (no bias)
//   gridDim.z == 1, OutH==0   : fp32 C = acc + bias
//   gridDim.z == 1, OutH!=0   : bf16 split planes = split((acc+bias)*oscale)
// ===========================================================================
#define ROWB 80
#define TILE_BYTES (128*ROWB)
#define STAGE_BYTES (4*TILE_BYTES)
#define GEMM_SMEM_BYTES (2*STAGE_BYTES)
#define GROUPM 16

__global__ void __launch_bounds__(256, 2)
gemm_bf16x3(const __nv_bfloat16* __restrict__ Ah, const __nv_bfloat16* __restrict__ Al,
            const __nv_bfloat16* __restrict__ Wh, const __nv_bfloat16* __restrict__ Wl,
            const float* __restrict__ bias, float* __restrict__ C,
            __nv_bfloat16* __restrict__ OutH, __nv_bfloat16* __restrict__ OutL,
            float oscale, int M, int N, int Kdim, int kLen)
{
    extern __shared__ char smem[];
    const uint32_t smem_base = smem_u32(smem);

    const int tid = threadIdx.x;
    const int lane = tid & 31;
    const int wid = tid >> 5;
    const int g = lane >> 2;
    const int t = lane & 3;
    const int wm = wid & 1;
    const int wn = wid >> 1;

    const int num_n = N >> 7;
    const int num_m = M >> 7;
    const int pid = blockIdx.x;
    const int width = GROUPM * num_n;
    const int gid = pid / width;
    const int first_m = gid * GROUPM;
    const int gsz = min(num_m - first_m, GROUPM);
    const int pid_m = first_m + (pid % gsz);
    const int pid_n = (pid % width) / gsz;
    const int m0 = pid_m << 7;
    const int n0 = pid_n << 7;
    const int kOff = blockIdx.z * kLen;

    float acc[4][4][4];
    #pragma unroll
    for (int i = 0; i < 4; i++)
        #pragma unroll
        for (int j = 0; j < 4; j++)
            #pragma unroll
            for (int r = 0; r < 4; r++) acc[i][j][r] = 0.f;

    const int nch = kLen >> 5;
    const int crow = tid >> 2;
    const int ccol = tid & 3;

    const int a_row_l = (lane & 7) + ((lane >> 3) & 1) * 8;
    const int a_k16   = (lane >> 4) * 16;
    const int b_row_l = (lane >> 4) * 8 + (lane & 7);
    const int b_k16   = ((lane >> 3) & 1) * 16;

    auto stage = [&](int cidx, uint32_t dstbase) {
        const size_t kb = (size_t)kOff + (size_t)cidx * 32 + ccol * 8;
        #pragma unroll
        for (int p = 0; p < 2; p++) {
            int r = crow + 64 * p;
            uint32_t d = dstbase + (uint32_t)(r * ROWB + ccol * 16);
            cp_async16(d,                 Ah + (size_t)(m0 + r) * Kdim + kb);
            cp_async16(d +   TILE_BYTES,  Al + (size_t)(m0 + r) * Kdim + kb);
            cp_async16(d + 2*TILE_BYTES,  Wh + (size_t)(n0 + r) * Kdim + kb);
            cp_async16(d + 3*TILE_BYTES,  Wl + (size_t)(n0 + r) * Kdim + kb);
        }
    };

    stage(0, smem_base);
    asm volatile("cp.async.commit_group;" ::: "memory");

    for (int c = 0; c < nch; c++) {
        if (c + 1 < nch) {
            stage(c + 1, smem_base + (uint32_t)((c + 1) & 1) * STAGE_BYTES);
            asm volatile("cp.async.commit_group;" ::: "memory");
            asm volatile("cp.async.wait_group 1;" ::: "memory");
        } else {
            asm volatile("cp.async.wait_group 0;" ::: "memory");
        }
        __syncthreads();

        const uint32_t sb = smem_base + (uint32_t)(c & 1) * STAGE_BYTES;
        const uint32_t aBase = sb + (uint32_t)((wm * 64 + a_row_l) * ROWB + a_k16);
        const uint32_t bBase = sb + 2*TILE_BYTES
                             + (uint32_t)((wn * 32 + b_row_l) * ROWB + b_k16);

        #pragma unroll
        for (int ks = 0; ks < 2; ks++) {
            uint32_t bh[4][2], bl[4][2];
            #pragma unroll
            for (int tnp = 0; tnp < 2; tnp++) {
                uint32_t ad = bBase + tnp * (16 * ROWB) + ks * 32;
                ldsm_x4(bh[2*tnp][0], bh[2*tnp][1], bh[2*tnp+1][0], bh[2*tnp+1][1], ad);
                ldsm_x4(bl[2*tnp][0], bl[2*tnp][1], bl[2*tnp+1][0], bl[2*tnp+1][1],
                        ad + TILE_BYTES);
            }
            #pragma unroll
            for (int mh = 0; mh < 2; mh++) {
                uint32_t ah[2][4], al[2][4];
                #pragma unroll
                for (int q = 0; q < 2; q++) {
                    uint32_t ad = aBase + (mh * 2 + q) * (16 * ROWB) + ks * 32;
                    ldsm_x4(ah[q][0], ah[q][1], ah[q][2], ah[q][3], ad);
                    ldsm_x4(al[q][0], al[q][1], al[q][2], al[q][3], ad + TILE_BYTES);
                }
                #pragma unroll
                for (int q = 0; q < 2; q++)
                    #pragma unroll
                    for (int tn = 0; tn < 4; tn++) {
                        float* d = acc[mh * 2 + q][tn];
                        mma_bf16(d, al[q], bh[tn]);
                        mma_bf16(d, ah[q], bl[tn]);
                        mma_bf16(d, ah[q], bh[tn]);
                    }
            }
        }
        __syncthreads();
    }

    // Epilogue
    const bool full = (gridDim.z == 1);
    if (full && OutH != nullptr) {
        #pragma unroll
        for (int mt = 0; mt < 4; mt++) {
            int row = m0 + wm * 64 + mt * 16 + g;
            #pragma unroll
            for (int tn = 0; tn < 4; tn++) {
                int col = n0 + wn * 32 + tn * 8 + t * 2;
                float2 bv = *(const float2*)(bias + col);
                float v0x = (acc[mt][tn][0] + bv.x) * oscale;
                float v0y = (acc[mt][tn][1] + bv.y) * oscale;
                float v1x = (acc[mt][tn][2] + bv.x) * oscale;
                float v1y = (acc[mt][tn][3] + bv.y) * oscale;
                __nv_bfloat16 h0,l0,h1,l1,h2,l2,h3,l3;
                spl(v0x,h0,l0); spl(v0y,h1,l1);
                spl(v1x,h2,l2); spl(v1y,h3,l3);
                *(uint32_t*)(OutH + (size_t)row * N + col)       = pk2(h0,h1);
                *(uint32_t*)(OutL + (size_t)row * N + col)       = pk2(l0,l1);
                *(uint32_t*)(OutH + (size_t)(row + 8) * N + col) = pk2(h2,h3);
                *(uint32_t*)(OutL + (size_t)(row + 8) * N + col) = pk2(l2,l3);
            }
        }
    } else {
        float* Cout = C + (full ? (size_t)0 : (size_t)blockIdx.z * M * N);
        #pragma unroll
        for (int mt = 0; mt < 4; mt++) {
            int row = m0 + wm * 64 + mt * 16 + g;
            #pragma unroll
            for (int tn = 0; tn < 4; tn++) {
                int col = n0 + wn * 32 + tn * 8 + t * 2;
                float bx = 0.f, by = 0.f;
                if (full) { float2 bv = *(const float2*)(bias + col); bx = bv.x; by = bv.y; }
                float2 v0, v1;
                v0.x = acc[mt][tn][0] + bx; v0.y = acc[mt][tn][1] + by;
                v1.x = acc[mt][tn][2] + bx; v1.y = acc[mt][tn][3] + by;
                *(float2*)(Cout + (size_t)row * N + col) = v0;
                *(float2*)(Cout + (size_t)(row + 8) * N + col) = v1;
            }
        }
    }
}

// Deterministic split-K=4 reduce for the merged K|V projection (N=256).
// part: 4 partials of [MTOT][256]; col<128 -> K (bias bk), col>=128 -> V (bias bv).
// Emits bf16 split planes for K and V.
__global__ void __launch_bounds__(256)
reduce4_kv_split(const float* __restrict__ part,
                 const float* __restrict__ bk, const float* __restrict__ bv,
                 __nv_bfloat16* __restrict__ KsH, __nv_bfloat16* __restrict__ KsL,
                 __nv_bfloat16* __restrict__ VsH, __nv_bfloat16* __restrict__ VsL,
                 int MN)
{
    int i = blockIdx.x * 256 + threadIdx.x;
    if (i < MN) {
        float v = (part[i] + part[(size_t)MN + i])
                + (part[(size_t)2*MN + i] + part[(size_t)3*MN + i]);
        int r = i >> 8, c = i & 255;
        __nv_bfloat16 h, l;
        if (c < 128) {
            spl(v + bk[c], h, l);
            KsH[(size_t)r*DD + c] = h;
            KsL[(size_t)r*DD + c] = l;
        } else {
            spl(v + bv[c - 128], h, l);
            VsH[(size_t)r*DD + (c - 128)] = h;
            VsL[(size_t)r*DD + (c - 128)] = l;
        }
    }
}

// ===========================================================================
// bf16x3 MMA flash attention, BKV=32 with DOUBLE-BUFFERED K/V stages
// (GEMM-style cp.async pipeline). 128 threads (4 warps), warp = 16 q-rows.
// Epilogue writes bf16 split planes in the scrambled layout.
// ===========================================================================
#define AT_STRIDE 272
#define AT_QT  (64*AT_STRIDE)            // 17408 (Q tile, 64 rows)
#define AT_KT  (32*AT_STRIDE)            // 8704  (K/V half tile, 32 rows)
#define AT_STG (4*AT_KT)                 // one stage: Kh,Kl,Vh,Vl = 34816
#define AT_SMEM (2*AT_QT + 2*AT_STG)     // 104448 -> 2 CTAs/SM

__global__ void __launch_bounds__(128, 2)
mqa_attn_mma(const __nv_bfloat16* __restrict__ Qh, const __nv_bfloat16* __restrict__ Ql,
             const __nv_bfloat16* __restrict__ Kh, const __nv_bfloat16* __restrict__ Kl,
             const __nv_bfloat16* __restrict__ Vh, const __nv_bfloat16* __restrict__ Vl,
             __nv_bfloat16* __restrict__ OH, __nv_bfloat16* __restrict__ OL)
{
    extern __shared__ char smem[];
    const uint32_t sb = smem_u32(smem);
    const int tid = threadIdx.x;
    const int w = tid >> 5;
    const int lane = tid & 31;
    const int g = lane >> 2, t = lane & 3;
    const int q0 = blockIdx.x * 64;
    const int h = blockIdx.y;
    const int b = blockIdx.z;

    const uint32_t SQh = sb, SQl = sb + AT_QT;
    const uint32_t STG0 = sb + 2*AT_QT;

    // Q tiles (hi/lo), loaded once (group 1)
    {
        const size_t qg = ((size_t)(b*SS + q0))*HH + (size_t)h*DD;
        for (int i = tid; i < 64*16; i += 128) {
            int r = i >> 4, ch = i & 15;
            size_t src = qg + (size_t)r*HH + ch*8;
            uint32_t dst = (uint32_t)(r*AT_STRIDE + ch*16);
            cp_async16(SQh + dst, Qh + src);
            cp_async16(SQl + dst, Ql + src);
        }
        asm volatile("cp.async.commit_group;" ::: "memory");
    }

    float m0 = -INFINITY, m1 = -INFINITY, l0 = 0.f, l1 = 0.f;
    float oacc[16][4];
    #pragma unroll
    for (int j = 0; j < 16; j++)
        #pragma unroll
        for (int r = 0; r < 4; r++) oacc[j][r] = 0.f;

    // per-lane fragment address components (within a tile)
    const uint32_t qa = SQh + (uint32_t)((w*16 + (lane&7) + ((lane>>3)&1)*8)*AT_STRIDE
                                         + ((lane>>4)&1)*16);
    const uint32_t kb_off = (uint32_t)(((lane>>4)*8 + (lane&7))*AT_STRIDE
                                       + ((lane>>3)&1)*16);
    const uint32_t va_off = (uint32_t)(((lane&7) + ((lane>>3)&1)*8)*AT_STRIDE
                                       + ((lane>>4)&1)*16);

    const size_t kvg0 = (size_t)(b*SS)*DD;

    auto stageKV = [&](int kt, uint32_t base) {
        for (int i = tid; i < 32*16; i += 128) {
            int r = i >> 4, ch = i & 15;
            size_t src = kvg0 + (size_t)(kt*32 + r)*DD + ch*8;
            uint32_t dst = base + (uint32_t)(r*AT_STRIDE + ch*16);
            cp_async16(dst,            Kh + src);
            cp_async16(dst +   AT_KT,  Kl + src);
            cp_async16(dst + 2*AT_KT,  Vh + src);
            cp_async16(dst + 3*AT_KT,  Vl + src);
        }
    };

    // prologue: stage chunk 0 (group 2)
    stageKV(0, STG0);
    asm volatile("cp.async.commit_group;" ::: "memory");

    const int NCH = SS / 32;   // 64
    for (int kt = 0; kt < NCH; kt++) {
        if (kt + 1 < NCH) {
            stageKV(kt + 1, STG0 + (uint32_t)((kt + 1) & 1) * AT_STG);
            asm volatile("cp.async.commit_group;" ::: "memory");
            asm volatile("cp.async.wait_group 1;" ::: "memory");
        } else {
            asm volatile("cp.async.wait_group 0;" ::: "memory");
        }
        __syncthreads();

        const uint32_t st = STG0 + (uint32_t)(kt & 1) * AT_STG;
        const uint32_t kbase = st + kb_off;              // K hi tile
        const uint32_t vbase = st + 2*AT_KT + va_off;    // V hi tile

        // ---- S = Q @ K^T (x3), per-warp 16x32
        float sacc[4][4];
        #pragma unroll
        for (int j = 0; j < 4; j++)
            #pragma unroll
            for (int r = 0; r < 4; r++) sacc[j][r] = 0.f;

        #pragma unroll
        for (int ks = 0; ks < 8; ks++) {
            uint32_t qh_[4], ql_[4];
            ldsm_x4(qh_[0], qh_[1], qh_[2], qh_[3], qa + ks*32);
            ldsm_x4(ql_[0], ql_[1], ql_[2], ql_[3], qa + AT_QT + ks*32);
            #pragma unroll
            for (int np = 0; np < 2; np++) {
                uint32_t kh4[4], kl4[4];
                uint32_t ad = kbase + np*(16*AT_STRIDE) + ks*32;
                ldsm_x4(kh4[0], kh4[1], kh4[2], kh4[3], ad);
                ldsm_x4(kl4[0], kl4[1], kl4[2], kl4[3], ad + AT_KT);
                mma_bf16(sacc[2*np],   ql_, &kh4[0]);
                mma_bf16(sacc[2*np],   qh_, &kl4[0]);
                mma_bf16(sacc[2*np],   qh_, &kh4[0]);
                mma_bf16(sacc[2*np+1], ql_, &kh4[2]);
                mma_bf16(sacc[2*np+1], qh_, &kl4[2]);
                mma_bf16(sacc[2*np+1], qh_, &kh4[2]);
            }
        }

        // ---- online softmax (rows g and g+8)
        float rx0 = -INFINITY, rx1 = -INFINITY;
        #pragma unroll
        for (int j = 0; j < 4; j++) {
            rx0 = fmaxf(rx0, fmaxf(sacc[j][0], sacc[j][1]));
            rx1 = fmaxf(rx1, fmaxf(sacc[j][2], sacc[j][3]));
        }
        rx0 = fmaxf(rx0, __shfl_xor_sync(0xffffffffu, rx0, 1));
        rx0 = fmaxf(rx0, __shfl_xor_sync(0xffffffffu, rx0, 2));
        rx1 = fmaxf(rx1, __shfl_xor_sync(0xffffffffu, rx1, 1));
        rx1 = fmaxf(rx1, __shfl_xor_sync(0xffffffffu, rx1, 2));
        float mn0 = fmaxf(m0, rx0), mn1 = fmaxf(m1, rx1);
        float a0 = __expf(m0 - mn0), a1 = __expf(m1 - mn1);
        m0 = mn0; m1 = mn1;
        float rs0 = 0.f, rs1 = 0.f;
        #pragma unroll
        for (int j = 0; j < 4; j++) {
            sacc[j][0] = __expf(sacc[j][0] - mn0);
            sacc[j][1] = __expf(sacc[j][1] - mn0);
            sacc[j][2] = __expf(sacc[j][2] - mn1);
            sacc[j][3] = __expf(sacc[j][3] - mn1);
            rs0 += sacc[j][0] + sacc[j][1];
            rs1 += sacc[j][2] + sacc[j][3];
        }
        rs0 += __shfl_xor_sync(0xffffffffu, rs0, 1);
        rs0 += __shfl_xor_sync(0xffffffffu, rs0, 2);
        rs1 += __shfl_xor_sync(0xffffffffu, rs1, 1);
        rs1 += __shfl_xor_sync(0xffffffffu, rs1, 2);
        l0 = l0*a0 + rs0; l1 = l1*a1 + rs1;
        #pragma unroll
        for (int j = 0; j < 16; j++) {
            oacc[j][0] *= a0; oacc[j][1] *= a0;
            oacc[j][2] *= a1; oacc[j][3] *= a1;
        }

        // ---- O += P @ V (x3); kk over 2 k16 groups (32 kv rows)
        #pragma unroll
        for (int kk = 0; kk < 2; kk++) {
            uint32_t ph[4], pl[4];
            {
                const float* s0 = sacc[2*kk];
                const float* s1 = sacc[2*kk+1];
                __nv_bfloat16 h8[8], l8[8];
                spl(s0[0], h8[0], l8[0]); spl(s0[1], h8[1], l8[1]);
                spl(s0[2], h8[2], l8[2]); spl(s0[3], h8[3], l8[3]);
                spl(s1[0], h8[4], l8[4]); spl(s1[1], h8[5], l8[5]);
                spl(s1[2], h8[6], l8[6]); spl(s1[3], h8[7], l8[7]);
                ph[0] = pk2(h8[0], h8[1]); ph[1] = pk2(h8[2], h8[3]);
                ph[2] = pk2(h8[4], h8[5]); ph[3] = pk2(h8[6], h8[7]);
                pl[0] = pk2(l8[0], l8[1]); pl[1] = pk2(l8[2], l8[3]);
                pl[2] = pk2(l8[4], l8[5]); pl[3] = pk2(l8[6], l8[7]);
            }
            #pragma unroll
            for (int dg = 0; dg < 8; dg++) {
                uint32_t vh4[4], vl4[4];
                uint32_t ad = vbase + kk*(16*AT_STRIDE) + dg*32;
                ldsm_x4_t(vh4[0], vh4[1], vh4[2], vh4[3], ad);
                ldsm_x4_t(vl4[0], vl4[1], vl4[2], vl4[3], ad + AT_KT);
                mma_bf16(oacc[2*dg],   pl, &vh4[0]);
                mma_bf16(oacc[2*dg],   ph, &vl4[0]);
                mma_bf16(oacc[2*dg],   ph, &vh4[0]);
                mma_bf16(oacc[2*dg+1], pl, &vh4[2]);
                mma_bf16(oacc[2*dg+1], ph, &vl4[2]);
                mma_bf16(oacc[2*dg+1], ph, &vh4[2]);
            }
        }
        __syncthreads();   // all warps done with this stage before it's restaged
    }

    // ---- epilogue: normalize, stage fp32, split-store scrambled planes
    float* stg = (float*)(smem + 2*AT_QT);   // overlays stage area (needs 33792 B)
    float i0 = 1.f / l0, i1 = 1.f / l1;
    #pragma unroll
    for (int j = 0; j < 16; j++) {
        int col = j*8 + t*2;
        *(float2*)&stg[(w*16 + g)*132 + col]     = make_float2(oacc[j][0]*i0, oacc[j][1]*i0);
        *(float2*)&stg[(w*16 + g + 8)*132 + col] = make_float2(oacc[j][2]*i1, oacc[j][3]*i1);
    }
    __syncthreads();

    const size_t obase = (size_t)b*SS*HH;
    for (int i = tid; i < 64*128; i += 128) {
        int d = i >> 6;
        int s = i & 63;
        size_t row = (size_t)h*64 + (d >> 1);
        size_t col = (size_t)(d & 1)*2048 + q0 + s;
        __nv_bfloat16 hh, ll;
        spl(stg[s*132 + d], hh, ll);
        OH[obase + row*HH + col] = hh;
        OL[obase + row*HH + col] = ll;
    }
}

// ---------------------------------------------------------------------------
extern "C" void kernel_launch(void* const* d_in, const int* in_sizes, int n_in,
                              void* d_out, int out_size)
{
    const float* X  = (const float*)d_in[0];
    const float* Wq = (const float*)d_in[1];
    const float* bq = (const float*)d_in[2];
    const float* Wk = (const float*)d_in[3];
    const float* bk = (const float*)d_in[4];
    const float* Wv = (const float*)d_in[5];
    const float* bv = (const float*)d_in[6];
    const float* Wo = (const float*)d_in[7];
    const float* bo = (const float*)d_in[8];
    float* out = (float*)d_out;

    float *Qbuf, *Abuf, *Pp;
    __nv_bfloat16 *Xs, *Wq_s, *Wo_s, *Wkv_s, *Ks, *Vs;
    cudaGetSymbolAddress((void**)&Qbuf, g_Q);
    cudaGetSymbolAddress((void**)&Abuf, g_attn);
    cudaGetSymbolAddress((void**)&Pp, g_part);
    cudaGetSymbolAddress((void**)&Xs, g_Asplit);
    cudaGetSymbolAddress((void**)&Wq_s, g_Wsplit);
    cudaGetSymbolAddress((void**)&Wo_s, g_Wsplit2);
    cudaGetSymbolAddress((void**)&Wkv_s, g_WsplitKV);
    cudaGetSymbolAddress((void**)&Ks, g_Ks);
    cudaGetSymbolAddress((void**)&Vs, g_Vs);

    __nv_bfloat16* Xh = Xs;
    __nv_bfloat16* Xl = Xs + (size_t)MTOT * HH;
    __nv_bfloat16* Wqh = Wq_s;  __nv_bfloat16* Wql = Wq_s + (size_t)HH * HH;
    __nv_bfloat16* Woh = Wo_s;  __nv_bfloat16* Wol = Wo_s + (size_t)HH * HH;
    // combined K|V weight planes: hi = [256][HH], lo follows
    __nv_bfloat16* Wkvh = Wkv_s;
    __nv_bfloat16* Wkvl = Wkv_s + (size_t)(2*DD) * HH;
    __nv_bfloat16* Ksh = Ks;    __nv_bfloat16* Ksl = Ks + (size_t)MTOT * DD;
    __nv_bfloat16* Vsh = Vs;    __nv_bfloat16* Vsl = Vs + (size_t)MTOT * DD;
    __nv_bfloat16* Qh = (__nv_bfloat16*)Qbuf;
    __nv_bfloat16* Qlp = Qh + (size_t)MTOT * HH;
    __nv_bfloat16* Aph = (__nv_bfloat16*)Abuf;
    __nv_bfloat16* Apl = Aph + (size_t)MTOT * HH;

    cudaFuncSetAttribute(gemm_bf16x3,
                         cudaFuncAttributeMaxDynamicSharedMemorySize, GEMM_SMEM_BYTES);
    cudaFuncSetAttribute(mqa_attn_mma,
                         cudaFuncAttributeMaxDynamicSharedMemorySize, AT_SMEM);

    const int nX8 = MTOT*HH/8, nWqo8 = HH*HH/8, nWkv8 = DD*HH/8;
    const float qscale = 0.08838834764831845f;   // 1/sqrt(128)

    // 0) input splits
    split_bf16<<<(nX8 + 255)/256, 256>>>(X, Xh, Xl, nX8, 1.f);
    split_bf16<<<(nWqo8 + 255)/256, 256>>>(Wq, Wqh, Wql, nWqo8, 1.f);
    split_bf16<<<(nWkv8 + 255)/256, 256>>>(Wk, Wkvh, Wkvl, nWkv8, 1.f);
    split_bf16<<<(nWkv8 + 255)/256, 256>>>(Wv, Wkvh + (size_t)DD*HH,
                                           Wkvl + (size_t)DD*HH, nWkv8, 1.f);
    split_bf16<<<(nWqo8 + 255)/256, 256>>>(Wo, Woh, Wol, nWqo8, 1.f);

    // 1) Q projection -> split planes directly, qscale folded
    gemm_bf16x3<<<dim3((HH/128)*(MTOT/128), 1, 1), 256, GEMM_SMEM_BYTES>>>(
        Xh, Xl, Wqh, Wql, bq, nullptr, Qh, Qlp, qscale, MTOT, HH, HH, HH);

    // 2) merged K|V projection (N=256, split-K=4 -> 256 CTAs) -> fused reduce
    gemm_bf16x3<<<dim3((256/128)*(MTOT/128), 1, 4), 256, GEMM_SMEM_BYTES>>>(
        Xh, Xl, Wkvh, Wkvl, nullptr, Pp, nullptr, nullptr, 1.f, MTOT, 256, HH, HH/4);
    reduce4_kv_split<<<(MTOT*256 + 255)/256, 256>>>(
        Pp, bk, bv, Ksh, Ksl, Vsh, Vsl, MTOT*256);

    // 3) MMA flash attention (pipelined KV) -> scrambled split planes
    mqa_attn_mma<<<dim3(SS/64, NHEAD, BB), 128, AT_SMEM>>>(
        Qh, Qlp, Ksh, Ksl, Vsh, Vsl, Aph, Apl);

    // 4) O projection -> fp32 final output + bias
    gemm_bf16x3<<<dim3((HH/128)*(MTOT/128), 1, 1), 256, GEMM_SMEM_BYTES>>>(
        Aph, Apl, Woh, Wol, bo, out, nullptr, nullptr, 1.f, MTOT, HH, HH, HH);
}

// round 17
// speedup vs baseline: 1.0218x; 1.0218x over previous
#include <cuda_runtime.h>
#include <cuda_bf16.h>
#include <cstdint>
#include <math.h>

// Problem constants
#define BB    2
#define SS    2048
#define HH    4096
#define NHEAD 32
#define DD    128
#define MTOT  (BB*SS)
#define NQKV  (HH + 2*DD)    // 4352 = 34 * 128

// Scratch (no cudaMalloc allowed)
__device__ float g_Q[(size_t)BB*SS*HH];        // 64 MB -> Q bf16 hi/lo planes
__device__ float g_attn[(size_t)BB*SS*HH];     // 64 MB -> attn bf16 hi/lo planes
__device__ __nv_bfloat16 g_Asplit[(size_t)2*MTOT*HH];   // X split (hi, lo planes)
__device__ __nv_bfloat16 g_Wqkv[(size_t)2*NQKV*HH];     // Wq|Wk|Wv combined split planes
__device__ __nv_bfloat16 g_Wsplit2[(size_t)2*HH*HH];    // Wo split
__device__ __nv_bfloat16 g_Ks[(size_t)2*MTOT*DD];       // K split planes
__device__ __nv_bfloat16 g_Vs[(size_t)2*MTOT*DD];       // V split planes

// ===========================================================================
// Helpers
// ===========================================================================
__device__ __forceinline__ uint32_t smem_u32(const void* p) {
    uint32_t a;
    asm("{ .reg .u64 t; cvta.to.shared.u64 t, %1; cvt.u32.u64 %0, t; }" : "=r"(a) : "l"(p));
    return a;
}
__device__ __forceinline__ void cp_async16(uint32_t dst, const void* src) {
    asm volatile("cp.async.cg.shared.global [%0], [%1], 16;" :: "r"(dst), "l"(src));
}
__device__ __forceinline__ void ldsm_x4(uint32_t& r0, uint32_t& r1, uint32_t& r2,
                                        uint32_t& r3, uint32_t addr) {
    asm volatile("ldmatrix.sync.aligned.m8n8.x4.shared.b16 {%0,%1,%2,%3}, [%4];"
                 : "=r"(r0), "=r"(r1), "=r"(r2), "=r"(r3) : "r"(addr));
}
__device__ __forceinline__ void ldsm_x4_t(uint32_t& r0, uint32_t& r1, uint32_t& r2,
                                          uint32_t& r3, uint32_t addr) {
    asm volatile("ldmatrix.sync.aligned.m8n8.x4.trans.shared.b16 {%0,%1,%2,%3}, [%4];"
                 : "=r"(r0), "=r"(r1), "=r"(r2), "=r"(r3) : "r"(addr));
}
// bf16 mma.sync: D(16x8) += A(16x16) @ B(8x16)^T, row.col, fp32 accum
__device__ __forceinline__ void mma_bf16(float* d, const uint32_t* a, const uint32_t* b) {
    asm volatile(
        "mma.sync.aligned.m16n8k16.row.col.f32.bf16.bf16.f32 "
        "{%0,%1,%2,%3}, {%4,%5,%6,%7}, {%8,%9}, {%0,%1,%2,%3};"
        : "+f"(d[0]), "+f"(d[1]), "+f"(d[2]), "+f"(d[3])
        : "r"(a[0]), "r"(a[1]), "r"(a[2]), "r"(a[3]), "r"(b[0]), "r"(b[1]));
}

__device__ __forceinline__ uint32_t pk2(__nv_bfloat16 a, __nv_bfloat16 b) {
    return (uint32_t)__bfloat16_as_ushort(a) | ((uint32_t)__bfloat16_as_ushort(b) << 16);
}
__device__ __forceinline__ void spl(float v, __nv_bfloat16& h, __nv_bfloat16& l) {
    h = __float2bfloat16(v);
    l = __float2bfloat16(v - __bfloat162float(h));
}

// ===========================================================================
// Pre-pass: split (scale * fp32) into two bf16 planes. 8 elems/thread.
// ===========================================================================
__global__ void __launch_bounds__(256)
split_bf16(const float* __restrict__ in, __nv_bfloat16* __restrict__ hi,
           __nv_bfloat16* __restrict__ lo, int n8, float scale)
{
    int i = blockIdx.x * 256 + threadIdx.x;
    if (i < n8) {
        const float4* p = (const float4*)in;
        float4 a = p[2*i], b = p[2*i+1];
        __nv_bfloat16 h[8], l[8];
        spl(a.x*scale, h[0], l[0]); spl(a.y*scale, h[1], l[1]);
        spl(a.z*scale, h[2], l[2]); spl(a.w*scale, h[3], l[3]);
        spl(b.x*scale, h[4], l[4]); spl(b.y*scale, h[5], l[5]);
        spl(b.z*scale, h[6], l[6]); spl(b.w*scale, h[7], l[7]);
        uint4 H, L;
        H.x = pk2(h[0], h[1]); H.y = pk2(h[2], h[3]);
        H.z = pk2(h[4], h[5]); H.w = pk2(h[6], h[7]);
        L.x = pk2(l[0], l[1]); L.y = pk2(l[2], l[3]);
        L.z = pk2(l[4], l[5]); L.w = pk2(l[6], l[7]);
        ((uint4*)hi)[i] = H;
        ((uint4*)lo)[i] = L;
    }
}

// ===========================================================================
// bf16x3 tensor-core GEMM (R12-validated core, GROUP_M raster).
// mode 0: fp32 C = acc + biasQ
// mode 1 (QKV): per-column demux:
//   col <  HH          : QH/QL    = split((acc + bq[col]) * qscale), row stride HH
//   col <  HH+DD       : KH/KL    = split( acc + bk[col-HH] ),       row stride DD
//   else               : VH/VL    = split( acc + bv[col-HH-DD] ),    row stride DD
// ===========================================================================
#define ROWB 80
#define TILE_BYTES (128*ROWB)
#define STAGE_BYTES (4*TILE_BYTES)
#define GEMM_SMEM_BYTES (2*STAGE_BYTES)
#define GROUPM 16

__global__ void __launch_bounds__(256, 2)
gemm_bf16x3(const __nv_bfloat16* __restrict__ Ah, const __nv_bfloat16* __restrict__ Al,
            const __nv_bfloat16* __restrict__ Wh, const __nv_bfloat16* __restrict__ Wl,
            const float* __restrict__ biasQ, const float* __restrict__ bk,
            const float* __restrict__ bv,
            float* __restrict__ C,
            __nv_bfloat16* __restrict__ QH, __nv_bfloat16* __restrict__ QL,
            __nv_bfloat16* __restrict__ KH, __nv_bfloat16* __restrict__ KL,
            __nv_bfloat16* __restrict__ VH, __nv_bfloat16* __restrict__ VL,
            float qscale, int M, int N, int Kdim, int mode)
{
    extern __shared__ char smem[];
    const uint32_t smem_base = smem_u32(smem);

    const int tid = threadIdx.x;
    const int lane = tid & 31;
    const int wid = tid >> 5;
    const int g = lane >> 2;
    const int t = lane & 3;
    const int wm = wid & 1;
    const int wn = wid >> 1;

    const int num_n = N >> 7;
    const int num_m = M >> 7;
    const int pid = blockIdx.x;
    const int width = GROUPM * num_n;
    const int gid = pid / width;
    const int first_m = gid * GROUPM;
    const int gsz = min(num_m - first_m, GROUPM);
    const int pid_m = first_m + (pid % gsz);
    const int pid_n = (pid % width) / gsz;
    const int m0 = pid_m << 7;
    const int n0 = pid_n << 7;

    float acc[4][4][4];
    #pragma unroll
    for (int i = 0; i < 4; i++)
        #pragma unroll
        for (int j = 0; j < 4; j++)
            #pragma unroll
            for (int r = 0; r < 4; r++) acc[i][j][r] = 0.f;

    const int nch = Kdim >> 5;
    const int crow = tid >> 2;
    const int ccol = tid & 3;

    const int a_row_l = (lane & 7) + ((lane >> 3) & 1) * 8;
    const int a_k16   = (lane >> 4) * 16;
    const int b_row_l = (lane >> 4) * 8 + (lane & 7);
    const int b_k16   = ((lane >> 3) & 1) * 16;

    auto stage = [&](int cidx, uint32_t dstbase) {
        const size_t kb = (size_t)cidx * 32 + ccol * 8;
        #pragma unroll
        for (int p = 0; p < 2; p++) {
            int r = crow + 64 * p;
            uint32_t d = dstbase + (uint32_t)(r * ROWB + ccol * 16);
            cp_async16(d,                 Ah + (size_t)(m0 + r) * Kdim + kb);
            cp_async16(d +   TILE_BYTES,  Al + (size_t)(m0 + r) * Kdim + kb);
            cp_async16(d + 2*TILE_BYTES,  Wh + (size_t)(n0 + r) * Kdim + kb);
            cp_async16(d + 3*TILE_BYTES,  Wl + (size_t)(n0 + r) * Kdim + kb);
        }
    };

    stage(0, smem_base);
    asm volatile("cp.async.commit_group;" ::: "memory");

    for (int c = 0; c < nch; c++) {
        if (c + 1 < nch) {
            stage(c + 1, smem_base + (uint32_t)((c + 1) & 1) * STAGE_BYTES);
            asm volatile("cp.async.commit_group;" ::: "memory");
            asm volatile("cp.async.wait_group 1;" ::: "memory");
        } else {
            asm volatile("cp.async.wait_group 0;" ::: "memory");
        }
        __syncthreads();

        const uint32_t sb = smem_base + (uint32_t)(c & 1) * STAGE_BYTES;
        const uint32_t aBase = sb + (uint32_t)((wm * 64 + a_row_l) * ROWB + a_k16);
        const uint32_t bBase = sb + 2*TILE_BYTES
                             + (uint32_t)((wn * 32 + b_row_l) * ROWB + b_k16);

        #pragma unroll
        for (int ks = 0; ks < 2; ks++) {
            uint32_t bh[4][2], bl[4][2];
            #pragma unroll
            for (int tnp = 0; tnp < 2; tnp++) {
                uint32_t ad = bBase + tnp * (16 * ROWB) + ks * 32;
                ldsm_x4(bh[2*tnp][0], bh[2*tnp][1], bh[2*tnp+1][0], bh[2*tnp+1][1], ad);
                ldsm_x4(bl[2*tnp][0], bl[2*tnp][1], bl[2*tnp+1][0], bl[2*tnp+1][1],
                        ad + TILE_BYTES);
            }
            #pragma unroll
            for (int mh = 0; mh < 2; mh++) {
                uint32_t ah[2][4], al[2][4];
                #pragma unroll
                for (int q = 0; q < 2; q++) {
                    uint32_t ad = aBase + (mh * 2 + q) * (16 * ROWB) + ks * 32;
                    ldsm_x4(ah[q][0], ah[q][1], ah[q][2], ah[q][3], ad);
                    ldsm_x4(al[q][0], al[q][1], al[q][2], al[q][3], ad + TILE_BYTES);
                }
                #pragma unroll
                for (int q = 0; q < 2; q++)
                    #pragma unroll
                    for (int tn = 0; tn < 4; tn++) {
                        float* d = acc[mh * 2 + q][tn];
                        mma_bf16(d, al[q], bh[tn]);
                        mma_bf16(d, ah[q], bl[tn]);
                        mma_bf16(d, ah[q], bh[tn]);
                    }
            }
        }
        __syncthreads();
    }

    // Epilogue
    if (mode == 1) {
        #pragma unroll
        for (int mt = 0; mt < 4; mt++) {
            int row = m0 + wm * 64 + mt * 16 + g;
            #pragma unroll
            for (int tn = 0; tn < 4; tn++) {
                int col = n0 + wn * 32 + tn * 8 + t * 2;
                float a0 = acc[mt][tn][0], a1 = acc[mt][tn][1];
                float a2 = acc[mt][tn][2], a3 = acc[mt][tn][3];
                __nv_bfloat16 h0,l0,h1,l1,h2,l2,h3,l3;
                if (col < HH) {
                    float2 bv2 = *(const float2*)(biasQ + col);
                    spl((a0 + bv2.x) * qscale, h0, l0);
                    spl((a1 + bv2.y) * qscale, h1, l1);
                    spl((a2 + bv2.x) * qscale, h2, l2);
                    spl((a3 + bv2.y) * qscale, h3, l3);
                    *(uint32_t*)(QH + (size_t)row * HH + col)       = pk2(h0,h1);
                    *(uint32_t*)(QL + (size_t)row * HH + col)       = pk2(l0,l1);
                    *(uint32_t*)(QH + (size_t)(row + 8) * HH + col) = pk2(h2,h3);
                    *(uint32_t*)(QL + (size_t)(row + 8) * HH + col) = pk2(l2,l3);
                } else if (col < HH + DD) {
                    int cc = col - HH;
                    float2 bv2 = *(const float2*)(bk + cc);
                    spl(a0 + bv2.x, h0, l0); spl(a1 + bv2.y, h1, l1);
                    spl(a2 + bv2.x, h2, l2); spl(a3 + bv2.y, h3, l3);
                    *(uint32_t*)(KH + (size_t)row * DD + cc)       = pk2(h0,h1);
                    *(uint32_t*)(KL + (size_t)row * DD + cc)       = pk2(l0,l1);
                    *(uint32_t*)(KH + (size_t)(row + 8) * DD + cc) = pk2(h2,h3);
                    *(uint32_t*)(KL + (size_t)(row + 8) * DD + cc) = pk2(l2,l3);
                } else {
                    int cc = col - HH - DD;
                    float2 bv2 = *(const float2*)(bv + cc);
                    spl(a0 + bv2.x, h0, l0); spl(a1 + bv2.y, h1, l1);
                    spl(a2 + bv2.x, h2, l2); spl(a3 + bv2.y, h3, l3);
                    *(uint32_t*)(VH + (size_t)row * DD + cc)       = pk2(h0,h1);
                    *(uint32_t*)(VL + (size_t)row * DD + cc)       = pk2(l0,l1);
                    *(uint32_t*)(VH + (size_t)(row + 8) * DD + cc) = pk2(h2,h3);
                    *(uint32_t*)(VL + (size_t)(row + 8) * DD + cc) = pk2(l2,l3);
                }
            }
        }
    } else {
        #pragma unroll
        for (int mt = 0; mt < 4; mt++) {
            int row = m0 + wm * 64 + mt * 16 + g;
            #pragma unroll
            for (int tn = 0; tn < 4; tn++) {
                int col = n0 + wn * 32 + tn * 8 + t * 2;
                float2 bv2 = *(const float2*)(biasQ + col);
                float2 v0, v1;
                v0.x = acc[mt][tn][0] + bv2.x; v0.y = acc[mt][tn][1] + bv2.y;
                v1.x = acc[mt][tn][2] + bv2.x; v1.y = acc[mt][tn][3] + bv2.y;
                *(float2*)(C + (size_t)row * N + col) = v0;
                *(float2*)(C + (size_t)(row + 8) * N + col) = v1;
            }
        }
    }
}

// ===========================================================================
// bf16x3 MMA flash attention (R13/R14-validated mainloop, BKV=64).
// Epilogue writes bf16 split planes in the scrambled layout (R15-validated).
// ===========================================================================
#define AT_STRIDE 272
#define AT_TILE  (64*AT_STRIDE)
#define AT_SMEM  (6*AT_TILE)

__global__ void __launch_bounds__(128, 2)
mqa_attn_mma(const __nv_bfloat16* __restrict__ Qh, const __nv_bfloat16* __restrict__ Ql,
             const __nv_bfloat16* __restrict__ Kh, const __nv_bfloat16* __restrict__ Kl,
             const __nv_bfloat16* __restrict__ Vh, const __nv_bfloat16* __restrict__ Vl,
             __nv_bfloat16* __restrict__ OH, __nv_bfloat16* __restrict__ OL)
{
    extern __shared__ char smem[];
    const uint32_t sb = smem_u32(smem);
    const int tid = threadIdx.x;
    const int w = tid >> 5;
    const int lane = tid & 31;
    const int g = lane >> 2, t = lane & 3;
    const int q0 = blockIdx.x * 64;
    const int h = blockIdx.y;
    const int b = blockIdx.z;

    const uint32_t SQh = sb, SQl = sb + AT_TILE, SKh = sb + 2*AT_TILE,
                   SKl = sb + 3*AT_TILE, SVh = sb + 4*AT_TILE, SVl = sb + 5*AT_TILE;

    {
        const size_t qg = ((size_t)(b*SS + q0))*HH + (size_t)h*DD;
        for (int i = tid; i < 64*16; i += 128) {
            int r = i >> 4, ch = i & 15;
            size_t src = qg + (size_t)r*HH + ch*8;
            uint32_t dst = (uint32_t)(r*AT_STRIDE + ch*16);
            cp_async16(SQh + dst, Qh + src);
            cp_async16(SQl + dst, Ql + src);
        }
        asm volatile("cp.async.commit_group;" ::: "memory");
    }

    float m0 = -INFINITY, m1 = -INFINITY, l0 = 0.f, l1 = 0.f;
    float oacc[16][4];
    #pragma unroll
    for (int j = 0; j < 16; j++)
        #pragma unroll
        for (int r = 0; r < 4; r++) oacc[j][r] = 0.f;

    const uint32_t qa = SQh + (uint32_t)((w*16 + (lane&7) + ((lane>>3)&1)*8)*AT_STRIDE
                                         + ((lane>>4)&1)*16);
    const uint32_t kb = SKh + (uint32_t)(((lane>>4)*8 + (lane&7))*AT_STRIDE
                                         + ((lane>>3)&1)*16);
    const uint32_t va = SVh + (uint32_t)(((lane&7) + ((lane>>3)&1)*8)*AT_STRIDE
                                         + ((lane>>4)&1)*16);

    const size_t kvg0 = (size_t)(b*SS)*DD;

    for (int kt = 0; kt < SS/64; kt++) {
        __syncthreads();
        for (int i = tid; i < 64*16; i += 128) {
            int r = i >> 4, ch = i & 15;
            size_t src = kvg0 + (size_t)(kt*64 + r)*DD + ch*8;
            uint32_t dst = (uint32_t)(r*AT_STRIDE + ch*16);
            cp_async16(SKh + dst, Kh + src);
            cp_async16(SKl + dst, Kl + src);
            cp_async16(SVh + dst, Vh + src);
            cp_async16(SVl + dst, Vl + src);
        }
        asm volatile("cp.async.commit_group;" ::: "memory");
        asm volatile("cp.async.wait_group 0;" ::: "memory");
        __syncthreads();

        float sacc[8][4];
        #pragma unroll
        for (int j = 0; j < 8; j++)
            #pragma unroll
            for (int r = 0; r < 4; r++) sacc[j][r] = 0.f;

        #pragma unroll
        for (int ks = 0; ks < 8; ks++) {
            uint32_t qh_[4], ql_[4];
            ldsm_x4(qh_[0], qh_[1], qh_[2], qh_[3], qa + ks*32);
            ldsm_x4(ql_[0], ql_[1], ql_[2], ql_[3], qa + AT_TILE + ks*32);
            #pragma unroll
            for (int np = 0; np < 4; np++) {
                uint32_t kh4[4], kl4[4];
                uint32_t ad = kb + np*(16*AT_STRIDE) + ks*32;
                ldsm_x4(kh4[0], kh4[1], kh4[2], kh4[3], ad);
                ldsm_x4(kl4[0], kl4[1], kl4[2], kl4[3], ad + AT_TILE);
                mma_bf16(sacc[2*np],   ql_, &kh4[0]);
                mma_bf16(sacc[2*np],   qh_, &kl4[0]);
                mma_bf16(sacc[2*np],   qh_, &kh4[0]);
                mma_bf16(sacc[2*np+1], ql_, &kh4[2]);
                mma_bf16(sacc[2*np+1], qh_, &kl4[2]);
                mma_bf16(sacc[2*np+1], qh_, &kh4[2]);
            }
        }

        float rx0 = -INFINITY, rx1 = -INFINITY;
        #pragma unroll
        for (int j = 0; j < 8; j++) {
            rx0 = fmaxf(rx0, fmaxf(sacc[j][0], sacc[j][1]));
            rx1 = fmaxf(rx1, fmaxf(sacc[j][2], sacc[j][3]));
        }
        rx0 = fmaxf(rx0, __shfl_xor_sync(0xffffffffu, rx0, 1));
        rx0 = fmaxf(rx0, __shfl_xor_sync(0xffffffffu, rx0, 2));
        rx1 = fmaxf(rx1, __shfl_xor_sync(0xffffffffu, rx1, 1));
        rx1 = fmaxf(rx1, __shfl_xor_sync(0xffffffffu, rx1, 2));
        float mn0 = fmaxf(m0, rx0), mn1 = fmaxf(m1, rx1);
        float a0 = __expf(m0 - mn0), a1 = __expf(m1 - mn1);
        m0 = mn0; m1 = mn1;
        float rs0 = 0.f, rs1 = 0.f;
        #pragma unroll
        for (int j = 0; j < 8; j++) {
            sacc[j][0] = __expf(sacc[j][0] - mn0);
            sacc[j][1] = __expf(sacc[j][1] - mn0);
            sacc[j][2] = __expf(sacc[j][2] - mn1);
            sacc[j][3] = __expf(sacc[j][3] - mn1);
            rs0 += sacc[j][0] + sacc[j][1];
            rs1 += sacc[j][2] + sacc[j][3];
        }
        rs0 += __shfl_xor_sync(0xffffffffu, rs0, 1);
        rs0 += __shfl_xor_sync(0xffffffffu, rs0, 2);
        rs1 += __shfl_xor_sync(0xffffffffu, rs1, 1);
        rs1 += __shfl_xor_sync(0xffffffffu, rs1, 2);
        l0 = l0*a0 + rs0; l1 = l1*a1 + rs1;
        #pragma unroll
        for (int j = 0; j < 16; j++) {
            oacc[j][0] *= a0; oacc[j][1] *= a0;
            oacc[j][2] *= a1; oacc[j][3] *= a1;
        }

        #pragma unroll
        for (int kk = 0; kk < 4; kk++) {
            uint32_t ph[4], pl[4];
            {
                const float* s0 = sacc[2*kk];
                const float* s1 = sacc[2*kk+1];
                __nv_bfloat16 h8[8], l8[8];
                spl(s0[0], h8[0], l8[0]); spl(s0[1], h8[1], l8[1]);
                spl(s0[2], h8[2], l8[2]); spl(s0[3], h8[3], l8[3]);
                spl(s1[0], h8[4], l8[4]); spl(s1[1], h8[5], l8[5]);
                spl(s1[2], h8[6], l8[6]); spl(s1[3], h8[7], l8[7]);
                ph[0] = pk2(h8[0], h8[1]); ph[1] = pk2(h8[2], h8[3]);
                ph[2] = pk2(h8[4], h8[5]); ph[3] = pk2(h8[6], h8[7]);
                pl[0] = pk2(l8[0], l8[1]); pl[1] = pk2(l8[2], l8[3]);
                pl[2] = pk2(l8[4], l8[5]); pl[3] = pk2(l8[6], l8[7]);
            }
            #pragma unroll
            for (int dg = 0; dg < 8; dg++) {
                uint32_t vh4[4], vl4[4];
                uint32_t ad = va + kk*(16*AT_STRIDE) + dg*32;
                ldsm_x4_t(vh4[0], vh4[1], vh4[2], vh4[3], ad);
                ldsm_x4_t(vl4[0], vl4[1], vl4[2], vl4[3], ad + AT_TILE);
                mma_bf16(oacc[2*dg],   pl, &vh4[0]);
                mma_bf16(oacc[2*dg],   ph, &vl4[0]);
                mma_bf16(oacc[2*dg],   ph, &vh4[0]);
                mma_bf16(oacc[2*dg+1], pl, &vh4[2]);
                mma_bf16(oacc[2*dg+1], ph, &vl4[2]);
                mma_bf16(oacc[2*dg+1], ph, &vh4[2]);
            }
        }
    }

    // ---- epilogue: normalize, stage fp32, split-store scrambled planes
    __syncthreads();
    float* stg = (float*)(smem + 2*AT_TILE);
    float i0 = 1.f / l0, i1 = 1.f / l1;
    #pragma unroll
    for (int j = 0; j < 16; j++) {
        int col = j*8 + t*2;
        *(float2*)&stg[(w*16 + g)*132 + col]     = make_float2(oacc[j][0]*i0, oacc[j][1]*i0);
        *(float2*)&stg[(w*16 + g + 8)*132 + col] = make_float2(oacc[j][2]*i1, oacc[j][3]*i1);
    }
    __syncthreads();

    const size_t obase = (size_t)b*SS*HH;
    for (int i = tid; i < 64*128; i += 128) {
        int d = i >> 6;
        int s = i & 63;
        size_t row = (size_t)h*64 + (d >> 1);
        size_t col = (size_t)(d & 1)*2048 + q0 + s;
        __nv_bfloat16 hh, ll;
        spl(stg[s*132 + d], hh, ll);
        OH[obase + row*HH + col] = hh;
        OL[obase + row*HH + col] = ll;
    }
}

// ---------------------------------------------------------------------------
extern "C" void kernel_launch(void* const* d_in, const int* in_sizes, int n_in,
                              void* d_out, int out_size)
{
    const float* X  = (const float*)d_in[0];
    const float* Wq = (const float*)d_in[1];
    const float* bq = (const float*)d_in[2];
    const float* Wk = (const float*)d_in[3];
    const float* bk = (const float*)d_in[4];
    const float* Wv = (const float*)d_in[5];
    const float* bv = (const float*)d_in[6];
    const float* Wo = (const float*)d_in[7];
    const float* bo = (const float*)d_in[8];
    float* out = (float*)d_out;

    float *Qbuf, *Abuf;
    __nv_bfloat16 *Xs, *Wqkv, *Wo_s, *Ks, *Vs;
    cudaGetSymbolAddress((void**)&Qbuf, g_Q);
    cudaGetSymbolAddress((void**)&Abuf, g_attn);
    cudaGetSymbolAddress((void**)&Xs, g_Asplit);
    cudaGetSymbolAddress((void**)&Wqkv, g_Wqkv);
    cudaGetSymbolAddress((void**)&Wo_s, g_Wsplit2);
    cudaGetSymbolAddress((void**)&Ks, g_Ks);
    cudaGetSymbolAddress((void**)&Vs, g_Vs);

    __nv_bfloat16* Xh = Xs;
    __nv_bfloat16* Xl = Xs + (size_t)MTOT * HH;
    // combined Wq|Wk|Wv planes: hi = [NQKV][HH], lo follows
    __nv_bfloat16* Wch = Wqkv;
    __nv_bfloat16* Wcl = Wqkv + (size_t)NQKV * HH;
    __nv_bfloat16* Woh = Wo_s;  __nv_bfloat16* Wol = Wo_s + (size_t)HH * HH;
    __nv_bfloat16* Ksh = Ks;    __nv_bfloat16* Ksl = Ks + (size_t)MTOT * DD;
    __nv_bfloat16* Vsh = Vs;    __nv_bfloat16* Vsl = Vs + (size_t)MTOT * DD;
    __nv_bfloat16* Qh = (__nv_bfloat16*)Qbuf;
    __nv_bfloat16* Qlp = Qh + (size_t)MTOT * HH;
    __nv_bfloat16* Aph = (__nv_bfloat16*)Abuf;
    __nv_bfloat16* Apl = Aph + (size_t)MTOT * HH;

    cudaFuncSetAttribute(gemm_bf16x3,
                         cudaFuncAttributeMaxDynamicSharedMemorySize, GEMM_SMEM_BYTES);
    cudaFuncSetAttribute(mqa_attn_mma,
                         cudaFuncAttributeMaxDynamicSharedMemorySize, AT_SMEM);

    const int nX8 = MTOT*HH/8, nWqo8 = HH*HH/8, nWkv8 = DD*HH/8;
    const float qscale = 0.08838834764831845f;   // 1/sqrt(128)

    // 0) input splits: X, Wq (rows 0..4095), Wk (rows 4096..4223),
    //    Wv (rows 4224..4351) of the combined buffer, Wo
    split_bf16<<<(nX8 + 255)/256, 256>>>(X, Xh, Xl, nX8, 1.f);
    split_bf16<<<(nWqo8 + 255)/256, 256>>>(Wq, Wch, Wcl, nWqo8, 1.f);
    split_bf16<<<(nWkv8 + 255)/256, 256>>>(Wk, Wch + (size_t)HH*HH,
                                           Wcl + (size_t)HH*HH, nWkv8, 1.f);
    split_bf16<<<(nWkv8 + 255)/256, 256>>>(Wv, Wch + (size_t)(HH+DD)*HH,
                                           Wcl + (size_t)(HH+DD)*HH, nWkv8, 1.f);
    split_bf16<<<(nWqo8 + 255)/256, 256>>>(Wo, Woh, Wol, nWqo8, 1.f);

    // 1) fused QKV projection (N=4352, full K) -> Q planes (qscale+bq),
    //    K planes (+bk), V planes (+bv), all bf16-split, directly
    gemm_bf16x3<<<dim3((NQKV/128)*(MTOT/128), 1, 1), 256, GEMM_SMEM_BYTES>>>(
        Xh, Xl, Wch, Wcl, bq, bk, bv, nullptr,
        Qh, Qlp, Ksh, Ksl, Vsh, Vsl, qscale, MTOT, NQKV, HH, 1);

    // 2) MMA flash attention -> scrambled split planes
    mqa_attn_mma<<<dim3(SS/64, NHEAD, BB), 128, AT_SMEM>>>(
        Qh, Qlp, Ksh, Ksl, Vsh, Vsl, Aph, Apl);

    // 3) O projection -> fp32 final output + bias
    gemm_bf16x3<<<dim3((HH/128)*(MTOT/128), 1, 1), 256, GEMM_SMEM_BYTES>>>(
        Aph, Apl, Woh, Wol, bo, nullptr, nullptr, out,
        nullptr, nullptr, nullptr, nullptr, nullptr, nullptr,
        1.f, MTOT, HH, HH, 0);
}